// round 12
// baseline (speedup 1.0000x reference)
#include <cuda_runtime.h>
#include <stddef.h>

// UniSAGE is fully linear => pull the final averaging functionals backwards.
// R12: take the reduction off the critical path. Everything that depends only
// on gath1 (p^T X, r2^T X, sums, the whole 5.6MB x_0 read) runs as EXTRA
// BLOCKS inside the scat2 launch (no streams needed). Only p2_raw^T X +
// sum(p2_raw) remains after gath2 -> tiny L2-hot reduce2 + ticket GEMV.

#define NV   100000
#define NE   200000
#define NNZt 800000
#define DIN  14
#define HID  128
#define WP   (1.0f / (float)NV)
#define WR   (1.0f / (float)NE)

#define BLK       256
#define NNZ_GRID  ((NNZt / 8 + BLK - 1) / BLK)    // 391 (8 incidences/thread)
#define NNZ_THREADS (NNZt / 8)                     // 100000
#define RED_GRID  ((NV / 2 + BLK - 1) / BLK)       // 196 (2 vertices/thread)

// -------- device scratch (allocation-free), zeroed by one memset ----
struct __align__(16) Scratch {
    float4 pv4[NV];    // {p_raw, r2_raw, deg, pad}
    float  p2 [NV];    // p2_raw
    float2 ze [NE];    // {zp, edeg}
    float  zp2[NE];
    float  acc[32];    // [0..13]=p2^T X, [14..27]=r2^T X, 28=Σp, 29=Σp2, 30=Σr2
    unsigned int tick;
};
__device__ Scratch g_s;

__device__ __forceinline__ void red2(float2* a, float x, float y) {
    asm volatile("red.global.add.v2.f32 [%0], {%1,%2};" :: "l"(a), "f"(x), "f"(y) : "memory");
}
__device__ __forceinline__ void red1(float* a, float x) {
    asm volatile("red.global.add.f32 [%0], %1;" :: "l"(a), "f"(x) : "memory");
}

// ---- phase 1: vertex degrees into pv4[].z ----
__global__ void __launch_bounds__(BLK) k_deg(const int* __restrict__ rows) {
    int t = blockIdx.x * BLK + threadIdx.x;
    if (t >= NNZ_THREADS) return;
    const int4* r4 = (const int4*)(rows) + t * 2;
    int4 r0 = r4[0], r1 = r4[1];
    red1(&g_s.pv4[r0.x].z, 1.f); red1(&g_s.pv4[r0.y].z, 1.f);
    red1(&g_s.pv4[r0.z].z, 1.f); red1(&g_s.pv4[r0.w].z, 1.f);
    red1(&g_s.pv4[r1.x].z, 1.f); red1(&g_s.pv4[r1.y].z, 1.f);
    red1(&g_s.pv4[r1.z].z, 1.f); red1(&g_s.pv4[r1.w].z, 1.f);
}

// ---- phase 2: ze[e] += { (1/NV)/deg[v], 1 } ----
__global__ void __launch_bounds__(BLK) k_scat1(const int* __restrict__ rows,
                                               const int* __restrict__ cols) {
    int t = blockIdx.x * BLK + threadIdx.x;
    if (t >= NNZ_THREADS) return;
    const int4* r4 = (const int4*)(rows) + t * 2;
    const int4* c4 = (const int4*)(cols) + t * 2;
    int4 r0 = r4[0], r1 = r4[1];
    int4 c0 = c4[0], c1 = c4[1];
    float d0 = __ldcg(&g_s.pv4[r0.x].z), d1 = __ldcg(&g_s.pv4[r0.y].z);
    float d2 = __ldcg(&g_s.pv4[r0.z].z), d3 = __ldcg(&g_s.pv4[r0.w].z);
    float d4 = __ldcg(&g_s.pv4[r1.x].z), d5 = __ldcg(&g_s.pv4[r1.y].z);
    float d6 = __ldcg(&g_s.pv4[r1.z].z), d7 = __ldcg(&g_s.pv4[r1.w].z);
    red2(&g_s.ze[c0.x], __fdividef(WP, d0), 1.f);
    red2(&g_s.ze[c0.y], __fdividef(WP, d1), 1.f);
    red2(&g_s.ze[c0.z], __fdividef(WP, d2), 1.f);
    red2(&g_s.ze[c0.w], __fdividef(WP, d3), 1.f);
    red2(&g_s.ze[c1.x], __fdividef(WP, d4), 1.f);
    red2(&g_s.ze[c1.y], __fdividef(WP, d5), 1.f);
    red2(&g_s.ze[c1.z], __fdividef(WP, d6), 1.f);
    red2(&g_s.ze[c1.w], __fdividef(WP, d7), 1.f);
}

// ---- phase 3: pv4[v].xy += { zp[e], edeg[e]/NE } ----
__global__ void __launch_bounds__(BLK) k_gath1(const int* __restrict__ rows,
                                               const int* __restrict__ cols) {
    int t = blockIdx.x * BLK + threadIdx.x;
    if (t >= NNZ_THREADS) return;
    const int4* r4 = (const int4*)(rows) + t * 2;
    const int4* c4 = (const int4*)(cols) + t * 2;
    int4 r0 = r4[0], r1 = r4[1];
    int4 c0 = c4[0], c1 = c4[1];
    float2 z0 = __ldcg(&g_s.ze[c0.x]), z1 = __ldcg(&g_s.ze[c0.y]);
    float2 z2 = __ldcg(&g_s.ze[c0.z]), z3 = __ldcg(&g_s.ze[c0.w]);
    float2 z4 = __ldcg(&g_s.ze[c1.x]), z5 = __ldcg(&g_s.ze[c1.y]);
    float2 z6 = __ldcg(&g_s.ze[c1.z]), z7 = __ldcg(&g_s.ze[c1.w]);
    red2((float2*)&g_s.pv4[r0.x], z0.x, z0.y * WR);
    red2((float2*)&g_s.pv4[r0.y], z1.x, z1.y * WR);
    red2((float2*)&g_s.pv4[r0.z], z2.x, z2.y * WR);
    red2((float2*)&g_s.pv4[r0.w], z3.x, z3.y * WR);
    red2((float2*)&g_s.pv4[r1.x], z4.x, z4.y * WR);
    red2((float2*)&g_s.pv4[r1.y], z5.x, z5.y * WR);
    red2((float2*)&g_s.pv4[r1.z], z6.x, z6.y * WR);
    red2((float2*)&g_s.pv4[r1.w], z7.x, z7.y * WR);
}

// ---- phase 4 (MERGED): blocks [0,391) do scat2; blocks [391,587) do
//      reduce1 = p^T X, r2^T X, Σp, Σr2 (all final after gath1) ----
__global__ void __launch_bounds__(BLK)
k_scat2_red1(const int* __restrict__ rows, const int* __restrict__ cols,
             const float* __restrict__ x0) {
    if (blockIdx.x < NNZ_GRID) {
        // ----- scat2: zp2[e] += (p_raw[v]+WP)/deg[v] -----
        int t = blockIdx.x * BLK + threadIdx.x;
        if (t >= NNZ_THREADS) return;
        const int4* r4 = (const int4*)(rows) + t * 2;
        const int4* c4 = (const int4*)(cols) + t * 2;
        int4 r0 = r4[0], r1 = r4[1];
        int4 c0 = c4[0], c1 = c4[1];
        float4 v0 = __ldcg(&g_s.pv4[r0.x]), v1 = __ldcg(&g_s.pv4[r0.y]);
        float4 v2 = __ldcg(&g_s.pv4[r0.z]), v3 = __ldcg(&g_s.pv4[r0.w]);
        float4 v4 = __ldcg(&g_s.pv4[r1.x]), v5 = __ldcg(&g_s.pv4[r1.y]);
        float4 v6 = __ldcg(&g_s.pv4[r1.z]), v7 = __ldcg(&g_s.pv4[r1.w]);
        red1(&g_s.zp2[c0.x], __fdividef(v0.x + WP, v0.z));
        red1(&g_s.zp2[c0.y], __fdividef(v1.x + WP, v1.z));
        red1(&g_s.zp2[c0.z], __fdividef(v2.x + WP, v2.z));
        red1(&g_s.zp2[c0.w], __fdividef(v3.x + WP, v3.z));
        red1(&g_s.zp2[c1.x], __fdividef(v4.x + WP, v4.z));
        red1(&g_s.zp2[c1.y], __fdividef(v5.x + WP, v5.z));
        red1(&g_s.zp2[c1.z], __fdividef(v6.x + WP, v6.z));
        red1(&g_s.zp2[c1.w], __fdividef(v7.x + WP, v7.z));
        return;
    }

    // ----- reduce1: 2 vertices/thread; accumulate p^T X, r2^T X, Σp, Σr2 -----
    int t = (blockIdx.x - NNZ_GRID) * BLK + threadIdx.x;
    float vals[30];
#pragma unroll
    for (int k = 0; k < 30; k++) vals[k] = 0.f;

    if (t < NV / 2) {
        int v0 = 2 * t;
        float4 pa = g_s.pv4[v0];
        float4 pb = g_s.pv4[v0 + 1];
        float pvA = pa.x + WP;              // p = p_raw + 1/NV
        float r2A = pa.y + pa.z * WR;       // r2 = r2_raw + deg/NE
        float pvB = pb.x + WP;
        float r2B = pb.y + pb.z * WR;

        const float4* xr = (const float4*)(x0 + (long long)v0 * DIN);
        float xs[28];
#pragma unroll
        for (int q = 0; q < 7; q++) {
            float4 f = xr[q];
            xs[q * 4 + 0] = f.x; xs[q * 4 + 1] = f.y;
            xs[q * 4 + 2] = f.z; xs[q * 4 + 3] = f.w;
        }
#pragma unroll
        for (int j = 0; j < DIN; j++) {
            vals[j]      = pvA * xs[j] + pvB * xs[14 + j];   // p^T X
            vals[14 + j] = r2A * xs[j] + r2B * xs[14 + j];   // r2^T X
        }
        vals[28] = pvA + pvB;   // Σp
        vals[29] = r2A + r2B;   // Σr2
    }
#pragma unroll
    for (int k = 0; k < 30; k++) {
#pragma unroll
        for (int off = 16; off > 0; off >>= 1)
            vals[k] += __shfl_down_sync(0xffffffffu, vals[k], off);
    }
    __shared__ float sh[8 * 30];
    int warp = threadIdx.x >> 5, lane = threadIdx.x & 31;
    if (lane == 0) {
#pragma unroll
        for (int k = 0; k < 30; k++) sh[warp * 30 + k] = vals[k];
    }
    __syncthreads();
    if (threadIdx.x < 30) {
        float s = 0.f;
#pragma unroll
        for (int w = 0; w < 8; w++) s += sh[w * 30 + threadIdx.x];
        if (threadIdx.x < 28) {
            atomicAdd(&g_s.acc[threadIdx.x], s);       // p^T X -> acc[0..13] (partial of p2^T X)
        } else if (threadIdx.x == 28) {
            atomicAdd(&g_s.acc[28], s);                // Σp
            atomicAdd(&g_s.acc[29], s);                // Σp part of Σp2
        } else {
            atomicAdd(&g_s.acc[30], s);                // Σr2
        }
    }
}

// ---- phase 5: p2[v] += zp2[e] ----
__global__ void __launch_bounds__(BLK) k_gath2(const int* __restrict__ rows,
                                               const int* __restrict__ cols) {
    int t = blockIdx.x * BLK + threadIdx.x;
    if (t >= NNZ_THREADS) return;
    const int4* r4 = (const int4*)(rows) + t * 2;
    const int4* c4 = (const int4*)(cols) + t * 2;
    int4 r0 = r4[0], r1 = r4[1];
    int4 c0 = c4[0], c1 = c4[1];
    float z0 = __ldcg(&g_s.zp2[c0.x]), z1 = __ldcg(&g_s.zp2[c0.y]);
    float z2 = __ldcg(&g_s.zp2[c0.z]), z3 = __ldcg(&g_s.zp2[c0.w]);
    float z4 = __ldcg(&g_s.zp2[c1.x]), z5 = __ldcg(&g_s.zp2[c1.y]);
    float z6 = __ldcg(&g_s.zp2[c1.z]), z7 = __ldcg(&g_s.zp2[c1.w]);
    red1(&g_s.p2[r0.x], z0); red1(&g_s.p2[r0.y], z1);
    red1(&g_s.p2[r0.z], z2); red1(&g_s.p2[r0.w], z3);
    red1(&g_s.p2[r1.x], z4); red1(&g_s.p2[r1.y], z5);
    red1(&g_s.p2[r1.z], z6); red1(&g_s.p2[r1.w], z7);
}

// ---- phase 6: reduce2 (p2_raw^T X, Σp2_raw; X and p2 are L2-hot)
//      + ticket-fused final GEMV ----
__global__ void __launch_bounds__(BLK)
k_red2_final(const float* __restrict__ x0,
             const float* __restrict__ W0, const float* __restrict__ b0,
             const float* __restrict__ Wl0, const float* __restrict__ bl0,
             const float* __restrict__ Wl1, const float* __restrict__ bl1,
             const float* __restrict__ Wo0, const float* __restrict__ bo0,
             const float* __restrict__ Wo1, const float* __restrict__ bo1,
             float* __restrict__ out) {
    int t = blockIdx.x * BLK + threadIdx.x;
    float vals[15];
#pragma unroll
    for (int k = 0; k < 15; k++) vals[k] = 0.f;

    if (t < NV / 2) {
        int v0 = 2 * t;
        float2 pr = *(const float2*)&g_s.p2[v0];   // p2_raw pair
        const float4* xr = (const float4*)(x0 + (long long)v0 * DIN);
        float xs[28];
#pragma unroll
        for (int q = 0; q < 7; q++) {
            float4 f = xr[q];
            xs[q * 4 + 0] = f.x; xs[q * 4 + 1] = f.y;
            xs[q * 4 + 2] = f.z; xs[q * 4 + 3] = f.w;
        }
#pragma unroll
        for (int j = 0; j < DIN; j++)
            vals[j] = pr.x * xs[j] + pr.y * xs[14 + j];   // p2_raw^T X
        vals[14] = pr.x + pr.y;                            // Σp2_raw
    }
#pragma unroll
    for (int k = 0; k < 15; k++) {
#pragma unroll
        for (int off = 16; off > 0; off >>= 1)
            vals[k] += __shfl_down_sync(0xffffffffu, vals[k], off);
    }
    __shared__ float sh[8 * 15];
    int warp = threadIdx.x >> 5, lane = threadIdx.x & 31;
    if (lane == 0) {
#pragma unroll
        for (int k = 0; k < 15; k++) sh[warp * 15 + k] = vals[k];
    }
    __syncthreads();
    if (threadIdx.x < 15) {
        float s = 0.f;
#pragma unroll
        for (int w = 0; w < 8; w++) s += sh[w * 15 + threadIdx.x];
        if (threadIdx.x < 14) atomicAdd(&g_s.acc[threadIdx.x], s);  // completes p2^T X
        else                  atomicAdd(&g_s.acc[29], s);           // completes Σp2
    }

    // ---- ticket: last block runs the tiny GEMV chain ----
    __threadfence();
    __shared__ unsigned int is_last;
    if (threadIdx.x == 0)
        is_last = (atomicInc(&g_s.tick, gridDim.x - 1) == gridDim.x - 1) ? 1u : 0u;
    __syncthreads();
    if (!is_last) return;
    __threadfence();

    __shared__ float a0[HID], c0[HID], a1[HID], c1[HID], red[HID];
    int h = threadIdx.x;
    float sp  = g_s.acc[28];
    float sp2 = g_s.acc[29];
    float sr2 = g_s.acc[30];
    float sr  = (float)NNZt / (float)NE;   // 1^T (deg/NE) exactly

    if (h < HID) {
        float sa = 0.f, sc = 0.f;
#pragma unroll
        for (int j = 0; j < DIN; j++) {
            float w = W0[j * HID + h];
            sa += g_s.acc[j] * w;
            sc += g_s.acc[14 + j] * w;
        }
        a0[h] = sa + sp2 * b0[h];
        c0[h] = sc + sr2 * b0[h];
    }
    __syncthreads();
    if (h < HID) {
        float sa = 0.f, sc = 0.f;
        for (int m = 0; m < HID; m++) {
            float w = Wl0[m * HID + h];
            sa += a0[m] * w;
            sc += c0[m] * w;
        }
        a1[h] = sa + sp2 * bl0[h];
        c1[h] = sc + sr2 * bl0[h];
    }
    __syncthreads();
    if (h < HID) {
        float sa = 0.f, sc = 0.f;
        for (int m = 0; m < HID; m++) {
            float w = Wl1[m * HID + h];
            sa += a1[m] * w;
            sc += c1[m] * w;
        }
        float a2h = sa + sp * bl1[h];   // p^T h2
        float c2h = sc + sr * bl1[h];   // r^T h2
        red[h] = a2h * Wo0[h] + c2h * Wo1[h];
    }
    __syncthreads();
    for (int s = HID / 2; s > 0; s >>= 1) {
        if (h < s) red[h] += red[h + s];
        __syncthreads();
    }
    if (h == 0) out[0] = red[0] + bo0[0] + bo1[0];
}

extern "C" void kernel_launch(void* const* d_in, const int* in_sizes, int n_in,
                              void* d_out, int out_size) {
    const float* x_0  = (const float*)d_in[0];
    const int*   rows = (const int*)d_in[2];
    const int*   cols = (const int*)d_in[3];
    const float* W0   = (const float*)d_in[4];
    const float* b0   = (const float*)d_in[5];
    const float* Wl0  = (const float*)d_in[8];
    const float* bl0  = (const float*)d_in[9];
    const float* Wl1  = (const float*)d_in[10];
    const float* bl1  = (const float*)d_in[11];
    const float* Wo0  = (const float*)d_in[12];
    const float* bo0  = (const float*)d_in[13];
    const float* Wo1  = (const float*)d_in[14];
    const float* bo1  = (const float*)d_in[15];
    float* out = (float*)d_out;

    void* p_s;
    cudaGetSymbolAddress(&p_s, g_s);
    cudaMemsetAsync(p_s, 0, sizeof(Scratch));

    k_deg  <<<NNZ_GRID, BLK>>>(rows);
    k_scat1<<<NNZ_GRID, BLK>>>(rows, cols);
    k_gath1<<<NNZ_GRID, BLK>>>(rows, cols);
    k_scat2_red1<<<NNZ_GRID + RED_GRID, BLK>>>(rows, cols, x_0);
    k_gath2<<<NNZ_GRID, BLK>>>(rows, cols);
    k_red2_final<<<RED_GRID, BLK>>>(x_0, W0, b0, Wl0, bl0, Wl1, bl1,
                                    Wo0, bo0, Wo1, bo1, out);
}